// round 5
// baseline (speedup 1.0000x reference)
#include <cuda_runtime.h>
#include <math.h>

// Problem constants
#define BB   8
#define CCH  64
#define HH   112
#define WW   112
#define MID  256
#define NTAP 25

// Tiling
#define TW   16
#define TH   16
#define PW   24          // TW + 8 halo
#define PH   24          // TH + 8 halo
#define CHK  8           // channel chunk
#define NCHK (CCH / CHK) // 8
#define NT   128         // threads per CTA

// Effective weights: duplicated (w,w) pairs, layout [c][tap][o(padded to 26)]
// padded so each tap row is 26*8 = 208 B -> 16B aligned for LDS.128
__device__ __align__(16) float g_weff2[CCH * NTAP * 26 * 2];
__device__ float g_beff[NTAP];

__device__ __forceinline__ unsigned long long ffma2(unsigned long long a,
                                                    unsigned long long x,
                                                    unsigned long long c) {
    unsigned long long d;
    asm("fma.rn.f32x2 %0, %1, %2, %3;" : "=l"(d) : "l"(a), "l"(x), "l"(c));
    return d;
}

__device__ __forceinline__ void unpack2(unsigned long long v, float& a, float& b) {
    asm("mov.b64 {%0,%1}, %2;" : "=f"(a), "=f"(b) : "l"(v));
}

__device__ __forceinline__ unsigned long long pack2(float a, float b) {
    unsigned long long v;
    asm("mov.b64 %0, {%1,%2};" : "=l"(v) : "f"(a), "f"(b));
    return v;
}

// Compose conv1 (5x5 dil-2) and conv2 (1x1) into one effective 25-output conv.
__global__ void k_precompute(const float* __restrict__ w1, const float* __restrict__ b1,
                             const float* __restrict__ w2, const float* __restrict__ b2) {
    int idx = blockIdx.x * blockDim.x + threadIdx.x;
    if (idx < CCH * NTAP * NTAP) {
        int o = idx % NTAP;
        int t = (idx / NTAP) % NTAP;
        int c = idx / (NTAP * NTAP);
        float s = 0.f;
        #pragma unroll 4
        for (int m = 0; m < MID; ++m)
            s = fmaf(w2[o * MID + m], w1[(m * CCH + c) * NTAP + t], s);
        int di = ((c * NTAP + t) * 26 + o) * 2;
        g_weff2[di]     = s;
        g_weff2[di + 1] = s;
    }
    if (idx < NTAP) {
        float s = b2[idx];
        for (int m = 0; m < MID; ++m) s = fmaf(w2[idx * MID + m], b1[m], s);
        g_beff[idx] = s;
    }
}

__device__ __forceinline__ void load_patch(float* sP, const float* __restrict__ xb,
                                           int cc, int gy0, int gx0, int tid) {
    #pragma unroll 1
    for (int i = tid; i < CHK * PH * PW; i += NT) {
        int c   = i / (PH * PW);
        int rem = i - c * (PH * PW);
        int r   = rem / PW;
        int col = rem - r * PW;
        int gr = gy0 - 4 + r;
        int gc = gx0 - 4 + col;
        float v = 0.f;
        if (gr >= 0 && gr < HH && gc >= 0 && gc < WW)
            v = xb[((cc * CHK + c) * HH + gr) * WW + gc];
        sP[i] = v;
    }
}

__global__ __launch_bounds__(NT, 3)
void k_main(const float* __restrict__ x, float* __restrict__ out) {
    extern __shared__ char sraw[];
    unsigned long long* sW = (unsigned long long*)sraw;               // CHK*25*26 u64
    float* sP = (float*)(sraw + (size_t)CHK * NTAP * 26 * 8);          // CHK*PH*PW f32

    const int b   = blockIdx.z;
    const int gx0 = blockIdx.x * TW;
    const int gy0 = blockIdx.y * TH;
    const int tid = threadIdx.x;
    const int pr  = tid >> 3;      // 0..15 output row in tile
    const int pc  = tid & 7;       // pixel-pair column (px = 2*pc, 2*pc+1)

    const float* xb = x + (size_t)b * CCH * HH * WW;

    unsigned long long acc[NTAP];
    #pragma unroll
    for (int o = 0; o < NTAP; ++o) acc[o] = 0ull;

    // ---------------- Phase 1: 25 logits per pixel ----------------
    #pragma unroll 1
    for (int cc = 0; cc < NCHK; ++cc) {
        load_patch(sP, xb, cc, gy0, gx0, tid);
        {   // stage duplicated weights for this channel chunk
            const float4* wg = (const float4*)(g_weff2 + (size_t)cc * (CHK * NTAP * 26 * 2));
            float4* ws = (float4*)sW;
            #pragma unroll 1
            for (int i = tid; i < CHK * NTAP * 26 * 2 / 4; i += NT) ws[i] = wg[i];
        }
        __syncthreads();

        const float* pb = sP + pr * PW + 2 * pc;
        #pragma unroll 1
        for (int c = 0; c < CHK; ++c) {
            const unsigned long long* wr = sW + c * (NTAP * 26);
            const float* pcc = pb + c * (PH * PW);
            #pragma unroll
            for (int t = 0; t < NTAP; ++t) {
                const int dy = (t / 5) * 2, dx = (t % 5) * 2;
                unsigned long long xv =
                    *(const unsigned long long*)(pcc + dy * PW + dx);
                const unsigned long long* wp = wr + t * 26;
                #pragma unroll
                for (int o = 0; o < 24; o += 2) {
                    ulonglong2 wv = *(const ulonglong2*)(wp + o);
                    acc[o]     = ffma2(wv.x, xv, acc[o]);
                    acc[o + 1] = ffma2(wv.y, xv, acc[o + 1]);
                }
                acc[24] = ffma2(wp[24], xv, acc[24]);
            }
        }
        __syncthreads();
    }

    // ---------------- Softmax over the 25 taps (per pixel) ----------------
    float p0[NTAP], p1[NTAP];
    #pragma unroll
    for (int o = 0; o < NTAP; ++o) {
        float a, q;
        unpack2(acc[o], a, q);
        float be = g_beff[o];
        p0[o] = a + be;
        p1[o] = q + be;
    }
    float m0 = p0[0], m1 = p1[0];
    #pragma unroll
    for (int o = 1; o < NTAP; ++o) { m0 = fmaxf(m0, p0[o]); m1 = fmaxf(m1, p1[o]); }
    float s0 = 0.f, s1 = 0.f;
    #pragma unroll
    for (int o = 0; o < NTAP; ++o) {
        p0[o] = __expf(p0[o] - m0);
        p1[o] = __expf(p1[o] - m1);
        s0 += p0[o];
        s1 += p1[o];
    }
    float r0 = 1.f / s0, r1 = 1.f / s1;
    #pragma unroll
    for (int o = 0; o < NTAP; ++o)
        acc[o] = pack2(p0[o] * r0, p1[o] * r1);   // acc now holds attention weights

    // ---------------- Phase 2: attention-weighted neighborhood sum ----------------
    #pragma unroll 1
    for (int cc = 0; cc < NCHK; ++cc) {
        load_patch(sP, xb, cc, gy0, gx0, tid);
        __syncthreads();

        const float* pb = sP + pr * PW + 2 * pc;
        #pragma unroll 1
        for (int c = 0; c < CHK; ++c) {
            const float* pcc = pb + c * (PH * PW);
            unsigned long long ov = 0ull;
            #pragma unroll
            for (int t = 0; t < NTAP; ++t) {
                const int dy = (t / 5) * 2, dx = (t % 5) * 2;
                unsigned long long xv =
                    *(const unsigned long long*)(pcc + dy * PW + dx);
                ov = ffma2(acc[t], xv, ov);
            }
            float2 o2;
            unpack2(ov, o2.x, o2.y);
            *(float2*)&out[(((size_t)b * CCH + cc * CHK + c) * HH + (gy0 + pr)) * WW
                           + gx0 + 2 * pc] = o2;
        }
        __syncthreads();
    }
}

extern "C" void kernel_launch(void* const* d_in, const int* in_sizes, int n_in,
                              void* d_out, int out_size) {
    const float* x  = (const float*)d_in[0];
    const float* w1 = (const float*)d_in[1];
    const float* b1 = (const float*)d_in[2];
    const float* w2 = (const float*)d_in[3];
    const float* b2 = (const float*)d_in[4];
    float* out = (float*)d_out;

    // Fold conv1 + conv2 into effective 25-output conv weights/bias.
    k_precompute<<<(CCH * NTAP * NTAP + 255) / 256, 256>>>(w1, b1, w2, b2);

    const int smem_bytes = CHK * NTAP * 26 * 8 + CHK * PH * PW * 4;  // 41600 + 18432 = 60032
    cudaFuncSetAttribute(k_main, cudaFuncAttributeMaxDynamicSharedMemorySize, smem_bytes);

    dim3 grid(WW / TW, HH / TH, BB);   // 7 x 7 x 8 = 392 CTAs
    k_main<<<grid, NT, smem_bytes>>>(x, out);
}

// round 7
// speedup vs baseline: 1.3300x; 1.3300x over previous
#include <cuda_runtime.h>
#include <math.h>

// Problem constants
#define BB   8
#define CCH  64
#define HH   112
#define WW   112
#define MID  256
#define NTAP 25

// Tiling
#define TW   16
#define TH   16
#define PW   24          // TW + 8 halo
#define PH   24          // TH + 8 halo
#define CHK  8           // channel chunk
#define NCHK (CCH / CHK) // 8
#define NT   128         // threads per CTA

#define WROW 28          // weight row: 25 outputs + 3 pad floats -> 112 B, 16B aligned
#define NACC 13          // 13 f32x2 accumulators cover outputs 0..25 (o=25 is pad)

// Effective weights, COMPACT layout: [c][tap][o(0..24) pad to 28 floats]
__device__ __align__(16) float g_w2o[CCH * NTAP * WROW];
__device__ float g_beff[NTAP];

__device__ __forceinline__ unsigned long long ffma2(unsigned long long a,
                                                    unsigned long long x,
                                                    unsigned long long c) {
    unsigned long long d;
    asm("fma.rn.f32x2 %0, %1, %2, %3;" : "=l"(d) : "l"(a), "l"(x), "l"(c));
    return d;
}

__device__ __forceinline__ void unpack2(unsigned long long v, float& a, float& b) {
    asm("mov.b64 {%0,%1}, %2;" : "=f"(a), "=f"(b) : "l"(v));
}

__device__ __forceinline__ unsigned long long pack2(float a, float b) {
    unsigned long long v;
    asm("mov.b64 %0, {%1,%2};" : "=l"(v) : "f"(a), "f"(b));
    return v;
}

__device__ __forceinline__ unsigned long long pack_dup(float a) {
    unsigned long long v;
    asm("mov.b64 %0, {%1,%1};" : "=l"(v) : "f"(a));
    return v;
}

// Compose conv1 (5x5 dil-2) and conv2 (1x1) into one effective 25-output conv.
__global__ void k_precompute(const float* __restrict__ w1, const float* __restrict__ b1,
                             const float* __restrict__ w2, const float* __restrict__ b2) {
    int idx = blockIdx.x * blockDim.x + threadIdx.x;
    if (idx < CCH * NTAP * NTAP) {
        int o = idx % NTAP;
        int t = (idx / NTAP) % NTAP;
        int c = idx / (NTAP * NTAP);
        float s = 0.f;
        #pragma unroll 4
        for (int m = 0; m < MID; ++m)
            s = fmaf(w2[o * MID + m], w1[(m * CCH + c) * NTAP + t], s);
        g_w2o[(c * NTAP + t) * WROW + o] = s;
    }
    if (idx < CCH * NTAP) {   // zero the 3 pad floats of each row
        int base = idx * WROW;
        g_w2o[base + 25] = 0.f;
        g_w2o[base + 26] = 0.f;
        g_w2o[base + 27] = 0.f;
    }
    if (idx < NTAP) {
        float s = b2[idx];
        for (int m = 0; m < MID; ++m) s = fmaf(w2[idx * MID + m], b1[m], s);
        g_beff[idx] = s;
    }
}

__device__ __forceinline__ void load_patch(float* sP, const float* __restrict__ xb,
                                           int cc, int gy0, int gx0, int tid) {
    #pragma unroll 1
    for (int i = tid; i < CHK * PH * PW; i += NT) {
        int c   = i / (PH * PW);
        int rem = i - c * (PH * PW);
        int r   = rem / PW;
        int col = rem - r * PW;
        int gr = gy0 - 4 + r;
        int gc = gx0 - 4 + col;
        float v = 0.f;
        if (gr >= 0 && gr < HH && gc >= 0 && gc < WW)
            v = xb[((cc * CHK + c) * HH + gr) * WW + gc];
        sP[i] = v;
    }
}

__global__ __launch_bounds__(NT, 3)
void k_main(const float* __restrict__ x, float* __restrict__ out) {
    extern __shared__ char sraw[];
    float* sWf = (float*)sraw;                                 // CHK*25*28 floats (22400 B)
    float* sP  = (float*)(sraw + CHK * NTAP * WROW * 4);       // CHK*PH*PW floats (18432 B)

    const int b   = blockIdx.z;
    const int gx0 = blockIdx.x * TW;
    const int gy0 = blockIdx.y * TH;
    const int tid = threadIdx.x;
    const int pr  = tid >> 3;      // 0..15 output row in tile
    const int pc  = tid & 7;       // pixel-pair column (px = 2*pc, 2*pc+1)

    const float* xb = x + (size_t)b * CCH * HH * WW;

    // Accumulators: acc0 = pixel 0, acc1 = pixel 1; each u64 holds logits (2j, 2j+1)
    unsigned long long acc0[NACC], acc1[NACC];
    #pragma unroll
    for (int j = 0; j < NACC; ++j) { acc0[j] = 0ull; acc1[j] = 0ull; }

    // ---------------- Phase 1: 25 logits per pixel ----------------
    #pragma unroll 1
    for (int cc = 0; cc < NCHK; ++cc) {
        load_patch(sP, xb, cc, gy0, gx0, tid);
        {   // stage compact weights for this channel chunk: 22400 B
            const float4* wg = (const float4*)(g_w2o + (size_t)cc * (CHK * NTAP * WROW));
            float4* ws = (float4*)sWf;
            #pragma unroll 1
            for (int i = tid; i < CHK * NTAP * WROW / 4; i += NT) ws[i] = wg[i];
        }
        __syncthreads();

        const float* pb = sP + pr * PW + 2 * pc;
        #pragma unroll 1
        for (int c = 0; c < CHK; ++c) {
            const float* wc  = sWf + c * (NTAP * WROW);
            const float* pcc = pb + c * (PH * PW);
            #pragma unroll
            for (int t = 0; t < NTAP; ++t) {
                const int dy = (t / 5) * 2, dx = (t % 5) * 2;
                unsigned long long xv =
                    *(const unsigned long long*)(pcc + dy * PW + dx);
                float x0, x1;
                unpack2(xv, x0, x1);
                unsigned long long xa = pack_dup(x0);
                unsigned long long xb2 = pack_dup(x1);
                const ulonglong2* wp = (const ulonglong2*)(wc + t * WROW);
                #pragma unroll
                for (int h = 0; h < 7; ++h) {
                    ulonglong2 wv = wp[h];           // LDS.128, warp-broadcast
                    acc0[2*h] = ffma2(wv.x, xa, acc0[2*h]);
                    acc1[2*h] = ffma2(wv.x, xb2, acc1[2*h]);
                    if (2*h + 1 < NACC) {
                        acc0[2*h+1] = ffma2(wv.y, xa, acc0[2*h+1]);
                        acc1[2*h+1] = ffma2(wv.y, xb2, acc1[2*h+1]);
                    }
                }
            }
        }
        __syncthreads();
    }

    // ---------------- Softmax over the 25 taps (per pixel) ----------------
    float p0[26], p1[26];
    #pragma unroll
    for (int j = 0; j < NACC; ++j) {
        unpack2(acc0[j], p0[2*j], p0[2*j+1]);
        unpack2(acc1[j], p1[2*j], p1[2*j+1]);
    }
    #pragma unroll
    for (int o = 0; o < NTAP; ++o) {
        float be = g_beff[o];
        p0[o] += be;
        p1[o] += be;
    }
    float m0 = p0[0], m1 = p1[0];
    #pragma unroll
    for (int o = 1; o < NTAP; ++o) { m0 = fmaxf(m0, p0[o]); m1 = fmaxf(m1, p1[o]); }
    float s0 = 0.f, s1 = 0.f;
    #pragma unroll
    for (int o = 0; o < NTAP; ++o) {
        p0[o] = __expf(p0[o] - m0);
        p1[o] = __expf(p1[o] - m1);
        s0 += p0[o];
        s1 += p1[o];
    }
    float r0 = 1.f / s0, r1 = 1.f / s1;

    // Repack per-tap attention weights as (k_px0, k_px1) pairs for phase 2
    unsigned long long ak[NTAP];
    #pragma unroll
    for (int t = 0; t < NTAP; ++t)
        ak[t] = pack2(p0[t] * r0, p1[t] * r1);

    // ---------------- Phase 2: attention-weighted neighborhood sum ----------------
    #pragma unroll 1
    for (int cc = 0; cc < NCHK; ++cc) {
        load_patch(sP, xb, cc, gy0, gx0, tid);
        __syncthreads();

        const float* pb = sP + pr * PW + 2 * pc;
        #pragma unroll 1
        for (int c = 0; c < CHK; ++c) {
            const float* pcc = pb + c * (PH * PW);
            // two interleaved chains to hide FFMA2 latency
            unsigned long long ov0 = 0ull, ov1 = 0ull;
            #pragma unroll
            for (int t = 0; t < NTAP - 1; t += 2) {
                const int dy0 = (t / 5) * 2,       dx0 = (t % 5) * 2;
                const int dy1 = ((t + 1) / 5) * 2, dx1 = ((t + 1) % 5) * 2;
                unsigned long long xv0 =
                    *(const unsigned long long*)(pcc + dy0 * PW + dx0);
                unsigned long long xv1 =
                    *(const unsigned long long*)(pcc + dy1 * PW + dx1);
                ov0 = ffma2(ak[t], xv0, ov0);
                ov1 = ffma2(ak[t + 1], xv1, ov1);
            }
            {   // tap 24
                unsigned long long xv =
                    *(const unsigned long long*)(pcc + 8 * PW + 8);
                ov0 = ffma2(ak[24], xv, ov0);
            }
            float a0, a1, b0v, b1v;
            unpack2(ov0, a0, a1);
            unpack2(ov1, b0v, b1v);
            float2 o2 = make_float2(a0 + b0v, a1 + b1v);
            *(float2*)&out[(((size_t)b * CCH + cc * CHK + c) * HH + (gy0 + pr)) * WW
                           + gx0 + 2 * pc] = o2;
        }
        __syncthreads();
    }
}

extern "C" void kernel_launch(void* const* d_in, const int* in_sizes, int n_in,
                              void* d_out, int out_size) {
    const float* x  = (const float*)d_in[0];
    const float* w1 = (const float*)d_in[1];
    const float* b1 = (const float*)d_in[2];
    const float* w2 = (const float*)d_in[3];
    const float* b2 = (const float*)d_in[4];
    float* out = (float*)d_out;

    // Fold conv1 + conv2 into effective 25-output conv weights/bias.
    k_precompute<<<(CCH * NTAP * NTAP + 255) / 256, 256>>>(w1, b1, w2, b2);

    const int smem_bytes = CHK * NTAP * WROW * 4 + CHK * PH * PW * 4; // 22400 + 18432 = 40832
    cudaFuncSetAttribute(k_main, cudaFuncAttributeMaxDynamicSharedMemorySize, smem_bytes);

    dim3 grid(WW / TW, HH / TH, BB);   // 7 x 7 x 8 = 392 CTAs
    k_main<<<grid, NT, smem_bytes>>>(x, out);
}